// round 11
// baseline (speedup 1.0000x reference)
#include <cuda_runtime.h>
#include <cuda_bf16.h>
#include <math.h>
#include <stdint.h>

#define BATCH 2
#define SEQ   2048
#define EMB   1024
#define NH    16
#define HD    64
#define M1    (BATCH*SEQ)   /* 4096 */
#define N1    (3*EMB)       /* 3072 */
#define KDIM  1024
#define PA    136           /* gemm smem pitch (words); 136%32==8 -> conflict-free frags */

// ---------------- device scratch (allocation-free rule) ----------------
__device__ uint32_t g_Qh [(size_t)BATCH*NH*SEQ*(HD/2)];  // [b,h,s][d/2] packed bf16 hi, pre-scaled
__device__ uint32_t g_Ql [(size_t)BATCH*NH*SEQ*(HD/2)];  // packed bf16 lo
__device__ uint32_t g_KTh[(size_t)BATCH*NH*(HD/2)*SEQ];  // [b,h,d/2,s] packed bf16 hi
__device__ uint32_t g_KTl[(size_t)BATCH*NH*(HD/2)*SEQ];  // packed bf16 lo
__device__ uint32_t g_Vt [(size_t)BATCH*NH*SEQ*HD];      // [b,h,s,d] tf32 words
__device__ float    g_cm [(size_t)BATCH*NH*16*32*128];   // per (bh,qtile,chunk,row) clamped chunk max

__device__ uint32_t g_xth [(size_t)(KDIM/2)*M1];         // x^T packed hi  [k/2][m]
__device__ uint32_t g_xtl [(size_t)(KDIM/2)*M1];
__device__ uint32_t g_aoth[(size_t)(KDIM/2)*M1];         // AO^T packed [k/2][m]
__device__ uint32_t g_aotl[(size_t)(KDIM/2)*M1];
__device__ uint32_t g_wqh [(size_t)(KDIM/2)*N1];         // Wqkv packed [k/2][n]
__device__ uint32_t g_wql [(size_t)(KDIM/2)*N1];
__device__ uint32_t g_woh [(size_t)(KDIM/2)*EMB];        // Wout packed [k/2][n]
__device__ uint32_t g_wol [(size_t)(KDIM/2)*EMB];

__device__ __forceinline__ uint32_t f2tf32(float v) {
    uint32_t r;
    asm("cvt.rna.tf32.f32 %0, %1;" : "=r"(r) : "f"(v));
    return r;
}

// split (v0,v1) -> packed bf16 hi/lo words; v0 (even k) in low half
__device__ __forceinline__ void split_pack(float v0, float v1,
                                           uint32_t& hi, uint32_t& lo)
{
    const __nv_bfloat16 h0 = __float2bfloat16(v0);
    const __nv_bfloat16 h1 = __float2bfloat16(v1);
    const __nv_bfloat16 l0 = __float2bfloat16(v0 - __bfloat162float(h0));
    const __nv_bfloat16 l1 = __float2bfloat16(v1 - __bfloat162float(h1));
    hi = ((uint32_t)__bfloat16_as_ushort(h1) << 16) | __bfloat16_as_ushort(h0);
    lo = ((uint32_t)__bfloat16_as_ushort(l1) << 16) | __bfloat16_as_ushort(l0);
}

#define MMA16(C, A0, A1, A2, A3, B0, B1)                                      \
    asm volatile(                                                             \
        "mma.sync.aligned.m16n8k16.row.col.f32.bf16.bf16.f32 "                \
        "{%0,%1,%2,%3}, {%4,%5,%6,%7}, {%8,%9}, {%0,%1,%2,%3};"               \
        : "+f"((C)[0]), "+f"((C)[1]), "+f"((C)[2]), "+f"((C)[3])              \
        : "r"(A0), "r"(A1), "r"(A2), "r"(A3), "r"(B0), "r"(B1))

#define MMA8(C, A0, A1, A2, A3, B0, B1)                                       \
    asm volatile(                                                             \
        "mma.sync.aligned.m16n8k8.row.col.f32.tf32.tf32.f32 "                 \
        "{%0,%1,%2,%3}, {%4,%5,%6,%7}, {%8,%9}, {%0,%1,%2,%3};"               \
        : "+f"((C)[0]), "+f"((C)[1]), "+f"((C)[2]), "+f"((C)[3])              \
        : "r"(A0), "r"(A1), "r"(A2), "r"(A3), "r"(B0), "r"(B1))

#define CPA16(dst_u32, src_ptr)                                               \
    asm volatile("cp.async.cg.shared.global [%0], [%1], 16;"                  \
                 :: "r"(dst_u32), "l"(src_ptr))

// ---------------------------------------------------------------------------
// Prep: W[k][n] fp32 -> packed bf16 hi/lo [k/2][n]
// ---------------------------------------------------------------------------
__global__ __launch_bounds__(256)
void split_w(const float* __restrict__ W, uint32_t* __restrict__ Wh,
             uint32_t* __restrict__ Wl, int N, int total4)
{
    const int i = blockIdx.x * 256 + threadIdx.x;
    if (i >= total4) return;
    const int nw4 = N >> 2;
    const int kp = i / nw4;
    const int n0 = (i - kp * nw4) * 4;
    const float4 r0 = *(const float4*)&W[(size_t)(2 * kp) * N + n0];
    const float4 r1 = *(const float4*)&W[(size_t)(2 * kp + 1) * N + n0];
    uint32_t h[4], l[4];
    split_pack(r0.x, r1.x, h[0], l[0]);
    split_pack(r0.y, r1.y, h[1], l[1]);
    split_pack(r0.z, r1.z, h[2], l[2]);
    split_pack(r0.w, r1.w, h[3], l[3]);
    *(uint4*)&Wh[(size_t)kp * N + n0] = make_uint4(h[0], h[1], h[2], h[3]);
    *(uint4*)&Wl[(size_t)kp * N + n0] = make_uint4(l[0], l[1], l[2], l[3]);
}

// ---------------------------------------------------------------------------
// Prep: X[m][k] fp32 -> packed bf16 hi/lo transposed [k/2][m]
// ---------------------------------------------------------------------------
__global__ __launch_bounds__(256)
void split_t(const float* __restrict__ X, uint32_t* __restrict__ XTh,
             uint32_t* __restrict__ XTl, int M, int K)
{
    __shared__ float t[32][33];
    const int k0 = blockIdx.x * 32;
    const int m0 = blockIdx.y * 32;
    const int tx = threadIdx.x & 31, ty = threadIdx.x >> 5;
#pragma unroll
    for (int i = 0; i < 4; i++)
        t[ty + i * 8][tx] = X[(size_t)(m0 + ty + i * 8) * K + k0 + tx];
    __syncthreads();
#pragma unroll
    for (int i = 0; i < 2; i++) {
        const int kp = ty + i * 8;             // 0..15
        uint32_t hi, lo;
        split_pack(t[tx][2 * kp], t[tx][2 * kp + 1], hi, lo);
        const size_t dst = (size_t)(k0 / 2 + kp) * M + m0 + tx;
        XTh[dst] = hi;
        XTl[dst] = lo;
    }
}

// ---------------------------------------------------------------------------
// 3xBF16 GEMM on pre-split packed operands, cp.async double-buffered.
// (unchanged from R10)
// ---------------------------------------------------------------------------
template<int MODE>
__global__ __launch_bounds__(256, 2)
void gemm_bf(const uint32_t* __restrict__ APh, const uint32_t* __restrict__ APl,
             const uint32_t* __restrict__ BPh, const uint32_t* __restrict__ BPl,
             const float* __restrict__ bias, float* __restrict__ Cout,
             int M, int N, int K)
{
    extern __shared__ uint32_t smu[];
    uint32_t* sAh = smu;                   // [2][16*PA]
    uint32_t* sAl = sAh + 2 * 16 * PA;
    uint32_t* sBh = sAl + 2 * 16 * PA;
    uint32_t* sBl = sBh + 2 * 16 * PA;

    const int tid  = threadIdx.x;
    const int lane = tid & 31;
    const int wid  = tid >> 5;
    const int mw   = (wid >> 2) * 64;
    const int nw   = (wid & 3) * 32;
    const int g    = lane >> 2;
    const int tig  = lane & 3;
    const int bm   = blockIdx.y * 128;
    const int bn   = blockIdx.x * 128;

    const uint32_t bAh = (uint32_t)__cvta_generic_to_shared(sAh);
    const uint32_t bAl = (uint32_t)__cvta_generic_to_shared(sAl);
    const uint32_t bBh = (uint32_t)__cvta_generic_to_shared(sBh);
    const uint32_t bBl = (uint32_t)__cvta_generic_to_shared(sBl);

    const int c0k = (tid + 0)   >> 5, c0m = ((tid + 0)   & 31) * 4;
    const int c1k = (tid + 256) >> 5, c1m = ((tid + 256) & 31) * 4;

    auto issue = [&](int kt) {
        const int buf = kt & 1;
        const int ko2 = kt * 16;               // word-row offset
        {
            const size_t ga = (size_t)(ko2 + c0k) * M + bm + c0m;
            const size_t gb = (size_t)(ko2 + c0k) * N + bn + c0m;
            const uint32_t so = (uint32_t)(buf * 16 * PA + c0k * PA + c0m) * 4u;
            CPA16(bAh + so, APh + ga);
            CPA16(bAl + so, APl + ga);
            CPA16(bBh + so, BPh + gb);
            CPA16(bBl + so, BPl + gb);
        }
        {
            const size_t ga = (size_t)(ko2 + c1k) * M + bm + c1m;
            const size_t gb = (size_t)(ko2 + c1k) * N + bn + c1m;
            const uint32_t so = (uint32_t)(buf * 16 * PA + c1k * PA + c1m) * 4u;
            CPA16(bAh + so, APh + ga);
            CPA16(bAl + so, APl + ga);
            CPA16(bBh + so, BPh + gb);
            CPA16(bBl + so, BPl + gb);
        }
        asm volatile("cp.async.commit_group;");
    };

    float c[4][4][4];
#pragma unroll
    for (int i = 0; i < 4; i++)
#pragma unroll
        for (int j = 0; j < 4; j++)
#pragma unroll
            for (int l = 0; l < 4; l++) c[i][j][l] = 0.f;

    const int NKT = K / 32;
    issue(0);

    for (int kt = 0; kt < NKT; kt++) {
        if (kt + 1 < NKT) {
            issue(kt + 1);
            asm volatile("cp.async.wait_group 1;");
        } else {
            asm volatile("cp.async.wait_group 0;");
        }
        __syncthreads();

        const int cur = kt & 1;
        const uint32_t* ah = sAh + cur * 16 * PA;
        const uint32_t* al = sAl + cur * 16 * PA;
        const uint32_t* bh = sBh + cur * 16 * PA;
        const uint32_t* bl = sBl + cur * 16 * PA;

#pragma unroll
        for (int ks2 = 0; ks2 < 16; ks2 += 8) {
            const int kp0 = ks2 + tig, kp1 = ks2 + tig + 4;
            uint32_t bhf[4][2], blf[4][2];
#pragma unroll
            for (int ni = 0; ni < 4; ni++) {
                const int n = nw + ni * 8 + g;
                bhf[ni][0] = bh[kp0 * PA + n];
                bhf[ni][1] = bh[kp1 * PA + n];
                blf[ni][0] = bl[kp0 * PA + n];
                blf[ni][1] = bl[kp1 * PA + n];
            }
#pragma unroll
            for (int mi = 0; mi < 4; mi++) {
                const int r0 = mw + mi * 16 + g, r1 = r0 + 8;
                const uint32_t ah0 = ah[kp0 * PA + r0];
                const uint32_t ah1 = ah[kp0 * PA + r1];
                const uint32_t ah2 = ah[kp1 * PA + r0];
                const uint32_t ah3 = ah[kp1 * PA + r1];
                const uint32_t al0 = al[kp0 * PA + r0];
                const uint32_t al1 = al[kp0 * PA + r1];
                const uint32_t al2 = al[kp1 * PA + r0];
                const uint32_t al3 = al[kp1 * PA + r1];
#pragma unroll
                for (int ni = 0; ni < 4; ni++) {
                    MMA16(c[mi][ni], ah0, ah1, ah2, ah3, bhf[ni][0], bhf[ni][1]);
                    MMA16(c[mi][ni], ah0, ah1, ah2, ah3, blf[ni][0], blf[ni][1]);
                    MMA16(c[mi][ni], al0, al1, al2, al3, bhf[ni][0], bhf[ni][1]);
                }
            }
        }
        __syncthreads();
    }

    // ---- epilogue ----
#pragma unroll
    for (int mi = 0; mi < 4; mi++) {
#pragma unroll
        for (int ni = 0; ni < 4; ni++) {
            const int r0 = bm + mw + mi * 16 + g;
            const int r1 = r0 + 8;
            const int n0 = bn + nw + ni * 8 + tig * 2;
            const float bv0 = bias[n0], bv1 = bias[n0 + 1];
            const float v00 = c[mi][ni][0] + bv0;
            const float v01 = c[mi][ni][1] + bv1;
            const float v10 = c[mi][ni][2] + bv0;
            const float v11 = c[mi][ni][3] + bv1;
            if (MODE == 1) {
                *(float2*)&Cout[(size_t)r0 * N + n0] = make_float2(v00, v01);
                *(float2*)&Cout[(size_t)r1 * N + n0] = make_float2(v10, v11);
            } else {
                const int type = n0 >> 10;
                const int e = n0 & (EMB - 1);
                const int h = e >> 6, d = e & 63;   // d even
#pragma unroll
                for (int rr = 0; rr < 2; rr++) {
                    const int m = rr ? r1 : r0;
                    const float va = rr ? v10 : v00;
                    const float vb = rr ? v11 : v01;
                    const int b = m >> 11, s = m & (SEQ - 1);
                    const size_t bhx = (size_t)(b * NH + h);
                    if (type == 0) {
                        uint32_t hi, lo;
                        split_pack(va * 0.125f, vb * 0.125f, hi, lo);
                        const size_t ix = (bhx * SEQ + s) * (HD / 2) + (d >> 1);
                        g_Qh[ix] = hi;
                        g_Ql[ix] = lo;
                    } else if (type == 1) {
                        uint32_t hi, lo;
                        split_pack(va, vb, hi, lo);
                        const size_t ix = (bhx * (HD / 2) + (d >> 1)) * SEQ + s;
                        g_KTh[ix] = hi;
                        g_KTl[ix] = lo;
                    } else {
                        *(uint2*)&g_Vt[(bhx * SEQ + s) * HD + d] = make_uint2(f2tf32(va), f2tf32(vb));
                    }
                }
            }
        }
    }
}

// ---------------------------------------------------------------------------
// Tensor-core causal attention, fused single compute pass (flash-style).
// Pass 1: K+V staged per chunk; S=QK^T (3xBF16, Q frags in REGISTERS);
//         E=exp(s-cmc) -> Estage -> coalesced gmem; O accumulated online:
//         co = co*exp(m_old-m_new) + (E@V)*exp(cmc-m_new)  (1x tf32 MMA).
// Pass 2: pure streaming: P = E * exp(cm-m)/l, cp.async double-buffered.
// ---------------------------------------------------------------------------
#define PQS 36   /* Q staging pitch (words) */
#define PKK 72   /* K packed pitch (words) */
#define PVV 72   /* V tf32 pitch */
#define PE  68   /* E fp32 pitch */
/* pass1 regions: */
#define O_K  0          /* KH 0..2304, KL 2304..4608 */
#define O_V  4608       /* 64*72 = 4608 */
#define O_ES 9216       /* 128*68 = 8704 -> ends 17920 */
/* pass2 overlay: E double buffer 2 x 8704 = 17408 @ 0 */
#define O_MR 17920
#define O_LI 18048
#define ATTN_SMEM_F 18176

__global__ __launch_bounds__(256)
void attn8(float* __restrict__ attw)
{
    extern __shared__ float smf[];
    uint32_t* smu = (uint32_t*)smf;

    const int tid  = threadIdx.x;
    const int lane = tid & 31;
    const int wid  = tid >> 5;
    const int g    = lane >> 2;
    const int tig  = lane & 3;
    const int band = wid * 16;
    const int q0   = (gridDim.x - 1 - blockIdx.x) * 128;  // heavy tiles first
    const int bh   = blockIdx.y;

    const uint32_t* Qhg = g_Qh + ((size_t)bh * SEQ + q0) * (HD / 2);
    const uint32_t* Qlg = g_Ql + ((size_t)bh * SEQ + q0) * (HD / 2);
    const size_t kb2 = (size_t)bh * (HD / 2) * SEQ;
    const size_t cb  = (((size_t)bh * 16) + (q0 >> 7)) * 32 * 128;

    const uint32_t sbase = (uint32_t)__cvta_generic_to_shared(smf);

    // ---- stage Q (temporarily in K+V region), hoist fragments to registers ----
#pragma unroll
    for (int i = 0; i < 4; i++) {
        const int idx = tid + i * 256;
        const int r = idx >> 3, c4 = idx & 7;
        *(uint4*)&smu[0    + r * PQS + c4 * 4] = *(const uint4*)&Qhg[(size_t)r * (HD / 2) + c4 * 4];
        *(uint4*)&smu[4608 + r * PQS + c4 * 4] = *(const uint4*)&Qlg[(size_t)r * (HD / 2) + c4 * 4];
    }
    __syncthreads();

    uint32_t qh[4][4], ql[4][4];
#pragma unroll
    for (int ks = 0; ks < 4; ks++) {
        const int kp0 = ks * 8 + tig, kp1 = kp0 + 4;
        qh[ks][0] = smu[0 + (band + g) * PQS + kp0];
        qh[ks][1] = smu[0 + (band + g + 8) * PQS + kp0];
        qh[ks][2] = smu[0 + (band + g) * PQS + kp1];
        qh[ks][3] = smu[0 + (band + g + 8) * PQS + kp1];
        ql[ks][0] = smu[4608 + (band + g) * PQS + kp0];
        ql[ks][1] = smu[4608 + (band + g + 8) * PQS + kp0];
        ql[ks][2] = smu[4608 + (band + g) * PQS + kp1];
        ql[ks][3] = smu[4608 + (band + g + 8) * PQS + kp1];
    }
    __syncthreads();   // Q staging region now free for K/V

    const int nch  = (q0 >> 6) + 2;
    const int row0 = q0 + band + g;
    const int row1 = row0 + 8;
    float* Prow = attw + ((size_t)bh * SEQ + q0) * SEQ;

    float m0 = -1e30f, m1 = -1e30f, l0 = 0.f, l1 = 0.f;
    float co[8][4];
#pragma unroll
    for (int df = 0; df < 8; df++)
#pragma unroll
        for (int j = 0; j < 4; j++) co[df][j] = 0.f;

    // =============== PASS 1: scores + E + online O accumulation ===============
    for (int kc = 0; kc < nch; kc++) {
        const int s0 = kc * 64;

        // stage K (hi+lo) and V for this chunk
#pragma unroll
        for (int i = 0; i < 2; i++) {
            const int idx = tid + i * 256;
            const int kp = idx >> 4, c4 = idx & 15;
            const size_t gk = kb2 + (size_t)kp * SEQ + s0 + c4 * 4;
            CPA16(sbase + (uint32_t)(O_K + kp * PKK + c4 * 4) * 4u, &g_KTh[gk]);
            CPA16(sbase + (uint32_t)(O_K + 2304 + kp * PKK + c4 * 4) * 4u, &g_KTl[gk]);
        }
#pragma unroll
        for (int i = 0; i < 4; i++) {
            const int idx = tid + i * 256;
            const int key = idx >> 4, c4 = idx & 15;
            CPA16(sbase + (uint32_t)(O_V + key * PVV + c4 * 4) * 4u,
                  &g_Vt[((size_t)bh * SEQ + s0 + key) * HD + c4 * 4]);
        }
        asm volatile("cp.async.commit_group;");
        asm volatile("cp.async.wait_group 0;");
        __syncthreads();   // K/V ready; prev chunk's Estage reads all done

        // ---- S = QK^T (3xBF16), Q from registers ----
        float sc[8][4];
#pragma unroll
        for (int nf = 0; nf < 8; nf++)
#pragma unroll
            for (int j = 0; j < 4; j++) sc[nf][j] = 0.f;

        const uint32_t* KH = smu + O_K;
        const uint32_t* KL = KH + 2304;
#pragma unroll
        for (int ks = 0; ks < 4; ks++) {
            const int kp0 = ks * 8 + tig, kp1 = kp0 + 4;
#pragma unroll
            for (int nf = 0; nf < 8; nf++) {
                const uint32_t kh0 = KH[kp0 * PKK + nf * 8 + g];
                const uint32_t kh1 = KH[kp1 * PKK + nf * 8 + g];
                const uint32_t kl0 = KL[kp0 * PKK + nf * 8 + g];
                const uint32_t kl1 = KL[kp1 * PKK + nf * 8 + g];
                MMA16(sc[nf], qh[ks][0], qh[ks][1], qh[ks][2], qh[ks][3], kh0, kh1);
                MMA16(sc[nf], qh[ks][0], qh[ks][1], qh[ks][2], qh[ks][3], kl0, kl1);
                MMA16(sc[nf], ql[ks][0], ql[ks][1], ql[ks][2], ql[ks][3], kh0, kh1);
            }
        }

        // ---- causal mask + chunk max ----
        float cm0 = -1e30f, cm1 = -1e30f;
#pragma unroll
        for (int nf = 0; nf < 8; nf++) {
            const int c01 = s0 + nf * 8 + 2 * tig;
            if (c01     > row0) sc[nf][0] = -1e30f;
            if (c01 + 1 > row0) sc[nf][1] = -1e30f;
            if (c01     > row1) sc[nf][2] = -1e30f;
            if (c01 + 1 > row1) sc[nf][3] = -1e30f;
            cm0 = fmaxf(cm0, fmaxf(sc[nf][0], sc[nf][1]));
            cm1 = fmaxf(cm1, fmaxf(sc[nf][2], sc[nf][3]));
        }
        cm0 = fmaxf(cm0, __shfl_xor_sync(0xffffffffu, cm0, 1));
        cm0 = fmaxf(cm0, __shfl_xor_sync(0xffffffffu, cm0, 2));
        cm1 = fmaxf(cm1, __shfl_xor_sync(0xffffffffu, cm1, 1));
        cm1 = fmaxf(cm1, __shfl_xor_sync(0xffffffffu, cm1, 2));
        const float cmc0 = fmaxf(cm0, -1e20f);
        const float cmc1 = fmaxf(cm1, -1e20f);

        // ---- E = exp(s - cmc) -> Estage; chunk sums ----
        float se0 = 0.f, se1 = 0.f;
#pragma unroll
        for (int nf = 0; nf < 8; nf++) {
            const float e0 = __expf(sc[nf][0] - cmc0);
            const float e1 = __expf(sc[nf][1] - cmc0);
            const float e2 = __expf(sc[nf][2] - cmc1);
            const float e3 = __expf(sc[nf][3] - cmc1);
            *(float2*)&smf[O_ES + (band + g) * PE + nf * 8 + 2 * tig]     = make_float2(e0, e1);
            *(float2*)&smf[O_ES + (band + g + 8) * PE + nf * 8 + 2 * tig] = make_float2(e2, e3);
            se0 += e0 + e1;
            se1 += e2 + e3;
        }
        se0 += __shfl_xor_sync(0xffffffffu, se0, 1);
        se0 += __shfl_xor_sync(0xffffffffu, se0, 2);
        se1 += __shfl_xor_sync(0xffffffffu, se1, 1);
        se1 += __shfl_xor_sync(0xffffffffu, se1, 2);

        // online (m,l) + rescale factors
        const float mn0 = fmaxf(m0, cm0), mn1 = fmaxf(m1, cm1);
        const float r0f = __expf(m0 - mn0), r1f = __expf(m1 - mn1);
        const float t0f = __expf(cmc0 - mn0), t1f = __expf(cmc1 - mn1);
        l0 = l0 * r0f + se0 * t0f;
        l1 = l1 * r1f + se1 * t1f;
        m0 = mn0; m1 = mn1;

        if (tig == 0) {
            g_cm[cb + (size_t)kc * 128 + band + g]     = cmc0;
            g_cm[cb + (size_t)kc * 128 + band + g + 8] = cmc1;
        }
        __syncthreads();   // all E rows visible (for copy-out)

        // ---- X = E @ V (1x tf32), online accumulate ----
        float X[8][4];
#pragma unroll
        for (int df = 0; df < 8; df++)
#pragma unroll
            for (int j = 0; j < 4; j++) X[df][j] = 0.f;

        const uint32_t* Vb = smu + O_V;
#pragma unroll
        for (int k8 = 0; k8 < 8; k8++) {
            const int ka = k8 * 8 + tig;
            const uint32_t a0 = f2tf32(smf[O_ES + (band + g) * PE + ka]);
            const uint32_t a1 = f2tf32(smf[O_ES + (band + g + 8) * PE + ka]);
            const uint32_t a2 = f2tf32(smf[O_ES + (band + g) * PE + ka + 4]);
            const uint32_t a3 = f2tf32(smf[O_ES + (band + g + 8) * PE + ka + 4]);
#pragma unroll
            for (int df = 0; df < 8; df++) {
                const uint32_t b0 = Vb[ka * PVV + df * 8 + g];
                const uint32_t b1 = Vb[(ka + 4) * PVV + df * 8 + g];
                MMA8(X[df], a0, a1, a2, a3, b0, b1);
            }
        }
#pragma unroll
        for (int df = 0; df < 8; df++) {
            co[df][0] = co[df][0] * r0f + X[df][0] * t0f;
            co[df][1] = co[df][1] * r0f + X[df][1] * t0f;
            co[df][2] = co[df][2] * r1f + X[df][2] * t1f;
            co[df][3] = co[df][3] * r1f + X[df][3] * t1f;
        }

        // ---- coalesced E copy-out ----
#pragma unroll
        for (int i = 0; i < 8; i++) {
            const int idx = tid + i * 256;
            const int r = idx >> 4, c4 = idx & 15;
            *(float4*)&Prow[(size_t)r * SEQ + s0 + c4 * 4] =
                *(const float4*)&smf[O_ES + r * PE + c4 * 4];
        }
    }

    // per-row final stats (O_MR/O_LI are outside all pass-1 regions)
    if (tig == 0) {
        smf[O_MR + band + g]     = m0;
        smf[O_MR + band + g + 8] = m1;
        smf[O_LI + band + g]     = 1.f / l0;
        smf[O_LI + band + g + 8] = 1.f / l1;
    }

    // ---- write O packed+transposed for gemm1 (normalize by l here) ----
    {
        const float il0 = 1.f / l0, il1 = 1.f / l1;
        const int b = bh >> 4, h = bh & 15;
        const int mm0 = b * SEQ + row0;
        const int mm1 = mm0 + 8;
#pragma unroll
        for (int df = 0; df < 8; df++) {
            const size_t kp = (size_t)(h * 32 + df * 4 + tig);
            uint32_t hi, lo;
            split_pack(co[df][0] * il0, co[df][1] * il0, hi, lo);
            g_aoth[kp * M1 + mm0] = hi;
            g_aotl[kp * M1 + mm0] = lo;
            split_pack(co[df][2] * il1, co[df][3] * il1, hi, lo);
            g_aoth[kp * M1 + mm1] = hi;
            g_aotl[kp * M1 + mm1] = lo;
        }
    }
    __syncthreads();   // pass-1 regions free; stats visible

    // =============== PASS 2: streaming normalize P = f * E ===============
    auto issue2 = [&](int kc) {
        const int buf = kc & 1;
        const int s0 = kc * 64;
#pragma unroll
        for (int i = 0; i < 8; i++) {
            const int idx = tid + i * 256;
            const int r = idx >> 4, c4 = idx & 15;
            const uint32_t so = (uint32_t)(buf * 8704 + r * PE + c4 * 4) * 4u;
            CPA16(sbase + so, &Prow[(size_t)r * SEQ + s0 + c4 * 4]);
        }
        asm volatile("cp.async.commit_group;");
    };

    issue2(0);

    for (int kc = 0; kc < nch; kc++) {
        const int s0 = kc * 64;
        if (kc + 1 < nch) {
            issue2(kc + 1);
            asm volatile("cp.async.wait_group 1;");
        } else {
            asm volatile("cp.async.wait_group 0;");
        }
        __syncthreads();   // buffer filled (all threads' copies)

        const float* Eb = smf + (kc & 1) * 8704;
#pragma unroll
        for (int i = 0; i < 8; i++) {
            const int idx = tid + i * 256;
            const int r = idx >> 4, c4 = idx & 15;
            const float f = __expf(g_cm[cb + (size_t)kc * 128 + r] - smf[O_MR + r]) * smf[O_LI + r];
            float4 e4 = *(const float4*)&Eb[r * PE + c4 * 4];
            e4.x *= f; e4.y *= f; e4.z *= f; e4.w *= f;
            *(float4*)&Prow[(size_t)r * SEQ + s0 + c4 * 4] = e4;
        }
        __syncthreads();   // reads done before buffer reuse at kc+2
    }

    // ---- zero tail of attention_weights ----
    {
        const int ztail = nch * 64;                // == q0 + 128
        const int ncol4 = (SEQ - ztail) >> 2;
        const float4 z = make_float4(0.f, 0.f, 0.f, 0.f);
        for (int idx = tid; idx < 128 * ncol4; idx += 256) {
            const int r = idx / ncol4, c = idx - r * ncol4;
            *(float4*)&Prow[(size_t)r * SEQ + ztail + c * 4] = z;
        }
    }
}

// ---------------------------------------------------------------------------
extern "C" void kernel_launch(void* const* d_in, const int* in_sizes, int n_in,
                              void* d_out, int out_size)
{
    const float* x    = (const float*)d_in[0];
    const float* Wqkv = (const float*)d_in[1];
    const float* bqkv = (const float*)d_in[2];
    const float* Wout = (const float*)d_in[3];
    const float* bout = (const float*)d_in[4];

    float* out  = (float*)d_out;
    float* attw = out + (size_t)BATCH * SEQ * EMB;

    uint32_t *p_xth, *p_xtl, *p_aoth, *p_aotl, *p_wqh, *p_wql, *p_woh, *p_wol;
    cudaGetSymbolAddress((void**)&p_xth,  g_xth);
    cudaGetSymbolAddress((void**)&p_xtl,  g_xtl);
    cudaGetSymbolAddress((void**)&p_aoth, g_aoth);
    cudaGetSymbolAddress((void**)&p_aotl, g_aotl);
    cudaGetSymbolAddress((void**)&p_wqh,  g_wqh);
    cudaGetSymbolAddress((void**)&p_wql,  g_wql);
    cudaGetSymbolAddress((void**)&p_woh,  g_woh);
    cudaGetSymbolAddress((void**)&p_wol,  g_wol);

    const int gsmem = 8 * 16 * PA * (int)sizeof(uint32_t);   // 69632
    cudaFuncSetAttribute(gemm_bf<0>, cudaFuncAttributeMaxDynamicSharedMemorySize, gsmem);
    cudaFuncSetAttribute(gemm_bf<1>, cudaFuncAttributeMaxDynamicSharedMemorySize, gsmem);
    const int asmem = ATTN_SMEM_F * (int)sizeof(float);      // 72704
    cudaFuncSetAttribute(attn8, cudaFuncAttributeMaxDynamicSharedMemorySize, asmem);

    // prep: pack weights + pack-transpose x
    split_w<<<((KDIM / 2) * (N1 / 4) + 255) / 256, 256>>>(Wqkv, p_wqh, p_wql, N1, (KDIM / 2) * (N1 / 4));
    split_w<<<((KDIM / 2) * (EMB / 4) + 255) / 256, 256>>>(Wout, p_woh, p_wol, EMB, (KDIM / 2) * (EMB / 4));
    split_t<<<dim3(KDIM / 32, M1 / 32), 256>>>(x, p_xth, p_xtl, M1, KDIM);

    // 1) QKV projection -> packed Q / packed K^T / tf32 V
    gemm_bf<0><<<dim3(N1 / 128, M1 / 128), 256, gsmem>>>(p_xth, p_xtl, p_wqh, p_wql, bqkv, nullptr, M1, N1, KDIM);

    // 2) fused causal attention (writes attention_weights + packed AO^T)
    attn8<<<dim3(SEQ / 128, BATCH * NH), 256, asmem>>>(attw);

    // 3) output projection
    gemm_bf<1><<<dim3(EMB / 128, M1 / 128), 256, gsmem>>>(p_aoth, p_aotl, p_woh, p_wol, bout, out, M1, EMB, KDIM);
}

// round 12
// speedup vs baseline: 1.2538x; 1.2538x over previous
#include <cuda_runtime.h>
#include <cuda_bf16.h>
#include <math.h>
#include <stdint.h>

#define BATCH 2
#define SEQ   2048
#define EMB   1024
#define NH    16
#define HD    64
#define M1    (BATCH*SEQ)   /* 4096 */
#define N1    (3*EMB)       /* 3072 */
#define KDIM  1024
#define PA    136           /* gemm smem pitch (words); 136%32==8 -> conflict-free frags */

// ---------------- device scratch (allocation-free rule) ----------------
__device__ uint32_t g_Qh [(size_t)BATCH*NH*SEQ*(HD/2)];  // [b,h,s][d/2] packed bf16 hi, pre-scaled
__device__ uint32_t g_Ql [(size_t)BATCH*NH*SEQ*(HD/2)];  // packed bf16 lo
__device__ uint32_t g_KTh[(size_t)BATCH*NH*(HD/2)*SEQ];  // [b,h,d/2,s] packed bf16 hi
__device__ uint32_t g_KTl[(size_t)BATCH*NH*(HD/2)*SEQ];  // packed bf16 lo
__device__ uint32_t g_Vt [(size_t)BATCH*NH*SEQ*HD];      // [b,h,s,d] tf32 words
__device__ float    g_cm [(size_t)BATCH*NH*16*32*128];   // per (bh,qtile,chunk,row) clamped chunk max

__device__ uint32_t g_xth [(size_t)(KDIM/2)*M1];         // x^T packed hi  [k/2][m]
__device__ uint32_t g_xtl [(size_t)(KDIM/2)*M1];
__device__ uint32_t g_aoth[(size_t)(KDIM/2)*M1];         // AO^T packed [k/2][m]
__device__ uint32_t g_aotl[(size_t)(KDIM/2)*M1];
__device__ uint32_t g_wqh [(size_t)(KDIM/2)*N1];         // Wqkv packed [k/2][n]
__device__ uint32_t g_wql [(size_t)(KDIM/2)*N1];
__device__ uint32_t g_woh [(size_t)(KDIM/2)*EMB];        // Wout packed [k/2][n]
__device__ uint32_t g_wol [(size_t)(KDIM/2)*EMB];

__device__ __forceinline__ uint32_t f2tf32(float v) {
    uint32_t r;
    asm("cvt.rna.tf32.f32 %0, %1;" : "=r"(r) : "f"(v));
    return r;
}

// split (v0,v1) -> packed bf16 hi/lo words; v0 (even k) in low half
__device__ __forceinline__ void split_pack(float v0, float v1,
                                           uint32_t& hi, uint32_t& lo)
{
    const __nv_bfloat16 h0 = __float2bfloat16(v0);
    const __nv_bfloat16 h1 = __float2bfloat16(v1);
    const __nv_bfloat16 l0 = __float2bfloat16(v0 - __bfloat162float(h0));
    const __nv_bfloat16 l1 = __float2bfloat16(v1 - __bfloat162float(h1));
    hi = ((uint32_t)__bfloat16_as_ushort(h1) << 16) | __bfloat16_as_ushort(h0);
    lo = ((uint32_t)__bfloat16_as_ushort(l1) << 16) | __bfloat16_as_ushort(l0);
}

#define MMA16(C, A0, A1, A2, A3, B0, B1)                                      \
    asm volatile(                                                             \
        "mma.sync.aligned.m16n8k16.row.col.f32.bf16.bf16.f32 "                \
        "{%0,%1,%2,%3}, {%4,%5,%6,%7}, {%8,%9}, {%0,%1,%2,%3};"               \
        : "+f"((C)[0]), "+f"((C)[1]), "+f"((C)[2]), "+f"((C)[3])              \
        : "r"(A0), "r"(A1), "r"(A2), "r"(A3), "r"(B0), "r"(B1))

#define MMA8(C, A0, A1, A2, A3, B0, B1)                                       \
    asm volatile(                                                             \
        "mma.sync.aligned.m16n8k8.row.col.f32.tf32.tf32.f32 "                 \
        "{%0,%1,%2,%3}, {%4,%5,%6,%7}, {%8,%9}, {%0,%1,%2,%3};"               \
        : "+f"((C)[0]), "+f"((C)[1]), "+f"((C)[2]), "+f"((C)[3])              \
        : "r"(A0), "r"(A1), "r"(A2), "r"(A3), "r"(B0), "r"(B1))

#define CPA16(dst_u32, src_ptr)                                               \
    asm volatile("cp.async.cg.shared.global [%0], [%1], 16;"                  \
                 :: "r"(dst_u32), "l"(src_ptr))

// ---------------------------------------------------------------------------
// Prep: W[k][n] fp32 -> packed bf16 hi/lo [k/2][n]
// ---------------------------------------------------------------------------
__global__ __launch_bounds__(256)
void split_w(const float* __restrict__ W, uint32_t* __restrict__ Wh,
             uint32_t* __restrict__ Wl, int N, int total4)
{
    const int i = blockIdx.x * 256 + threadIdx.x;
    if (i >= total4) return;
    const int nw4 = N >> 2;
    const int kp = i / nw4;
    const int n0 = (i - kp * nw4) * 4;
    const float4 r0 = *(const float4*)&W[(size_t)(2 * kp) * N + n0];
    const float4 r1 = *(const float4*)&W[(size_t)(2 * kp + 1) * N + n0];
    uint32_t h[4], l[4];
    split_pack(r0.x, r1.x, h[0], l[0]);
    split_pack(r0.y, r1.y, h[1], l[1]);
    split_pack(r0.z, r1.z, h[2], l[2]);
    split_pack(r0.w, r1.w, h[3], l[3]);
    *(uint4*)&Wh[(size_t)kp * N + n0] = make_uint4(h[0], h[1], h[2], h[3]);
    *(uint4*)&Wl[(size_t)kp * N + n0] = make_uint4(l[0], l[1], l[2], l[3]);
}

// ---------------------------------------------------------------------------
// Prep: X[m][k] fp32 -> packed bf16 hi/lo transposed [k/2][m]
// ---------------------------------------------------------------------------
__global__ __launch_bounds__(256)
void split_t(const float* __restrict__ X, uint32_t* __restrict__ XTh,
             uint32_t* __restrict__ XTl, int M, int K)
{
    __shared__ float t[32][33];
    const int k0 = blockIdx.x * 32;
    const int m0 = blockIdx.y * 32;
    const int tx = threadIdx.x & 31, ty = threadIdx.x >> 5;
#pragma unroll
    for (int i = 0; i < 4; i++)
        t[ty + i * 8][tx] = X[(size_t)(m0 + ty + i * 8) * K + k0 + tx];
    __syncthreads();
#pragma unroll
    for (int i = 0; i < 2; i++) {
        const int kp = ty + i * 8;             // 0..15
        uint32_t hi, lo;
        split_pack(t[tx][2 * kp], t[tx][2 * kp + 1], hi, lo);
        const size_t dst = (size_t)(k0 / 2 + kp) * M + m0 + tx;
        XTh[dst] = hi;
        XTl[dst] = lo;
    }
}

// ---------------------------------------------------------------------------
// 3xBF16 GEMM on pre-split packed operands, cp.async double-buffered.
// (unchanged from R10)
// ---------------------------------------------------------------------------
template<int MODE>
__global__ __launch_bounds__(256, 2)
void gemm_bf(const uint32_t* __restrict__ APh, const uint32_t* __restrict__ APl,
             const uint32_t* __restrict__ BPh, const uint32_t* __restrict__ BPl,
             const float* __restrict__ bias, float* __restrict__ Cout,
             int M, int N, int K)
{
    extern __shared__ uint32_t smu[];
    uint32_t* sAh = smu;                   // [2][16*PA]
    uint32_t* sAl = sAh + 2 * 16 * PA;
    uint32_t* sBh = sAl + 2 * 16 * PA;
    uint32_t* sBl = sBh + 2 * 16 * PA;

    const int tid  = threadIdx.x;
    const int lane = tid & 31;
    const int wid  = tid >> 5;
    const int mw   = (wid >> 2) * 64;
    const int nw   = (wid & 3) * 32;
    const int g    = lane >> 2;
    const int tig  = lane & 3;
    const int bm   = blockIdx.y * 128;
    const int bn   = blockIdx.x * 128;

    const uint32_t bAh = (uint32_t)__cvta_generic_to_shared(sAh);
    const uint32_t bAl = (uint32_t)__cvta_generic_to_shared(sAl);
    const uint32_t bBh = (uint32_t)__cvta_generic_to_shared(sBh);
    const uint32_t bBl = (uint32_t)__cvta_generic_to_shared(sBl);

    const int c0k = (tid + 0)   >> 5, c0m = ((tid + 0)   & 31) * 4;
    const int c1k = (tid + 256) >> 5, c1m = ((tid + 256) & 31) * 4;

    auto issue = [&](int kt) {
        const int buf = kt & 1;
        const int ko2 = kt * 16;               // word-row offset
        {
            const size_t ga = (size_t)(ko2 + c0k) * M + bm + c0m;
            const size_t gb = (size_t)(ko2 + c0k) * N + bn + c0m;
            const uint32_t so = (uint32_t)(buf * 16 * PA + c0k * PA + c0m) * 4u;
            CPA16(bAh + so, APh + ga);
            CPA16(bAl + so, APl + ga);
            CPA16(bBh + so, BPh + gb);
            CPA16(bBl + so, BPl + gb);
        }
        {
            const size_t ga = (size_t)(ko2 + c1k) * M + bm + c1m;
            const size_t gb = (size_t)(ko2 + c1k) * N + bn + c1m;
            const uint32_t so = (uint32_t)(buf * 16 * PA + c1k * PA + c1m) * 4u;
            CPA16(bAh + so, APh + ga);
            CPA16(bAl + so, APl + ga);
            CPA16(bBh + so, BPh + gb);
            CPA16(bBl + so, BPl + gb);
        }
        asm volatile("cp.async.commit_group;");
    };

    float c[4][4][4];
#pragma unroll
    for (int i = 0; i < 4; i++)
#pragma unroll
        for (int j = 0; j < 4; j++)
#pragma unroll
            for (int l = 0; l < 4; l++) c[i][j][l] = 0.f;

    const int NKT = K / 32;
    issue(0);

    for (int kt = 0; kt < NKT; kt++) {
        if (kt + 1 < NKT) {
            issue(kt + 1);
            asm volatile("cp.async.wait_group 1;");
        } else {
            asm volatile("cp.async.wait_group 0;");
        }
        __syncthreads();

        const int cur = kt & 1;
        const uint32_t* ah = sAh + cur * 16 * PA;
        const uint32_t* al = sAl + cur * 16 * PA;
        const uint32_t* bh = sBh + cur * 16 * PA;
        const uint32_t* bl = sBl + cur * 16 * PA;

#pragma unroll
        for (int ks2 = 0; ks2 < 16; ks2 += 8) {
            const int kp0 = ks2 + tig, kp1 = ks2 + tig + 4;
            uint32_t bhf[4][2], blf[4][2];
#pragma unroll
            for (int ni = 0; ni < 4; ni++) {
                const int n = nw + ni * 8 + g;
                bhf[ni][0] = bh[kp0 * PA + n];
                bhf[ni][1] = bh[kp1 * PA + n];
                blf[ni][0] = bl[kp0 * PA + n];
                blf[ni][1] = bl[kp1 * PA + n];
            }
#pragma unroll
            for (int mi = 0; mi < 4; mi++) {
                const int r0 = mw + mi * 16 + g, r1 = r0 + 8;
                const uint32_t ah0 = ah[kp0 * PA + r0];
                const uint32_t ah1 = ah[kp0 * PA + r1];
                const uint32_t ah2 = ah[kp1 * PA + r0];
                const uint32_t ah3 = ah[kp1 * PA + r1];
                const uint32_t al0 = al[kp0 * PA + r0];
                const uint32_t al1 = al[kp0 * PA + r1];
                const uint32_t al2 = al[kp1 * PA + r0];
                const uint32_t al3 = al[kp1 * PA + r1];
#pragma unroll
                for (int ni = 0; ni < 4; ni++) {
                    MMA16(c[mi][ni], ah0, ah1, ah2, ah3, bhf[ni][0], bhf[ni][1]);
                    MMA16(c[mi][ni], ah0, ah1, ah2, ah3, blf[ni][0], blf[ni][1]);
                    MMA16(c[mi][ni], al0, al1, al2, al3, bhf[ni][0], bhf[ni][1]);
                }
            }
        }
        __syncthreads();
    }

    // ---- epilogue ----
#pragma unroll
    for (int mi = 0; mi < 4; mi++) {
#pragma unroll
        for (int ni = 0; ni < 4; ni++) {
            const int r0 = bm + mw + mi * 16 + g;
            const int r1 = r0 + 8;
            const int n0 = bn + nw + ni * 8 + tig * 2;
            const float bv0 = bias[n0], bv1 = bias[n0 + 1];
            const float v00 = c[mi][ni][0] + bv0;
            const float v01 = c[mi][ni][1] + bv1;
            const float v10 = c[mi][ni][2] + bv0;
            const float v11 = c[mi][ni][3] + bv1;
            if (MODE == 1) {
                *(float2*)&Cout[(size_t)r0 * N + n0] = make_float2(v00, v01);
                *(float2*)&Cout[(size_t)r1 * N + n0] = make_float2(v10, v11);
            } else {
                const int type = n0 >> 10;
                const int e = n0 & (EMB - 1);
                const int h = e >> 6, d = e & 63;   // d even
#pragma unroll
                for (int rr = 0; rr < 2; rr++) {
                    const int m = rr ? r1 : r0;
                    const float va = rr ? v10 : v00;
                    const float vb = rr ? v11 : v01;
                    const int b = m >> 11, s = m & (SEQ - 1);
                    const size_t bhx = (size_t)(b * NH + h);
                    if (type == 0) {
                        uint32_t hi, lo;
                        split_pack(va * 0.125f, vb * 0.125f, hi, lo);
                        const size_t ix = (bhx * SEQ + s) * (HD / 2) + (d >> 1);
                        g_Qh[ix] = hi;
                        g_Ql[ix] = lo;
                    } else if (type == 1) {
                        uint32_t hi, lo;
                        split_pack(va, vb, hi, lo);
                        const size_t ix = (bhx * (HD / 2) + (d >> 1)) * SEQ + s;
                        g_KTh[ix] = hi;
                        g_KTl[ix] = lo;
                    } else {
                        *(uint2*)&g_Vt[(bhx * SEQ + s) * HD + d] = make_uint2(f2tf32(va), f2tf32(vb));
                    }
                }
            }
        }
    }
}

// ---------------------------------------------------------------------------
// Tensor-core causal attention, single QK^T pass (R10 structure).
// Pass 1: cp.async K double-buffer; E = exp(s - m_chunk) staged in smem,
//         stored coalesced to attw; chunk maxima -> g_cm; running (m,l).
// Pass 2: cp.async-prefetch E + V; P = f*E, write P; O += f * (E @ V).
// R12: __launch_bounds__(256, 2) — cap regs at 128 so 2 CTAs/SM co-reside
//      (smem 2x108.5KB fits in 227KB; registers were the occupancy blocker).
// ---------------------------------------------------------------------------
#define PQH 36   /* Q packed pitch (words) */
#define PKK 72   /* K packed pitch (words) */
#define PE  68   /* E fp32 pitch */
#define PVV 72   /* V tf32 pitch */
/* pass1 regions: */
#define O_QH 0          /* 128*36 = 4608 */
#define O_QL 4608       /* 4608 */
#define O_KD 9216       /* K double buffer: 2 x (KH 2304 + KL 2304) = 9216 */
#define O_ES 18432      /* E staging: 128*68 = 8704 -> total 27136 */
/* pass2 overlays: */
#define O_E  0          /* 2 x 128*68 = 17408 */
#define O_V2 17408      /* 2 x 64*72  = 9216  */
#define O_MF 26624
#define O_MR 26752
#define O_LI 26880
#define ATTN_SMEM_F 27136

__global__ __launch_bounds__(256, 2)
void attn7(float* __restrict__ attw)
{
    extern __shared__ float smf[];
    uint32_t* smu = (uint32_t*)smf;

    const int tid  = threadIdx.x;
    const int lane = tid & 31;
    const int wid  = tid >> 5;
    const int g    = lane >> 2;
    const int tig  = lane & 3;
    const int band = wid * 16;
    const int q0   = (gridDim.x - 1 - blockIdx.x) * 128;  // heavy tiles first
    const int bh   = blockIdx.y;

    const uint32_t* Qhg = g_Qh + ((size_t)bh * SEQ + q0) * (HD / 2);
    const uint32_t* Qlg = g_Ql + ((size_t)bh * SEQ + q0) * (HD / 2);
    const size_t kb2 = (size_t)bh * (HD / 2) * SEQ;
    const size_t cb  = (((size_t)bh * 16) + (q0 >> 7)) * 32 * 128;

    const uint32_t sbase = (uint32_t)__cvta_generic_to_shared(smf);

    // ---- Q tile copy (pre-packed, pre-scaled) ----
#pragma unroll
    for (int i = 0; i < 4; i++) {
        const int idx = tid + i * 256;
        const int r = idx >> 3, c4 = idx & 7;
        *(uint4*)&smu[O_QH + r * PQH + c4 * 4] = *(const uint4*)&Qhg[(size_t)r * (HD / 2) + c4 * 4];
        *(uint4*)&smu[O_QL + r * PQH + c4 * 4] = *(const uint4*)&Qlg[(size_t)r * (HD / 2) + c4 * 4];
    }

    const int nch  = (q0 >> 6) + 2;
    const int row0 = q0 + band + g;
    const int row1 = row0 + 8;
    float* Prow = attw + ((size_t)bh * SEQ + q0) * SEQ;

    float m0 = -1e30f, m1 = -1e30f, l0 = 0.f, l1 = 0.f;

    // =============================== PASS 1 ===============================
    // K chunk prefetch into double buffer
    auto issueK = [&](int kc) {
        const int buf = kc & 1;
        const int s0 = kc * 64;
#pragma unroll
        for (int i = 0; i < 2; i++) {
            const int idx = tid + i * 256;
            const int kp = idx >> 4, c4 = idx & 15;
            const size_t gk = kb2 + (size_t)kp * SEQ + s0 + c4 * 4;
            const uint32_t soH = (uint32_t)(O_KD + buf * 4608 + kp * PKK + c4 * 4) * 4u;
            const uint32_t soL = (uint32_t)(O_KD + buf * 4608 + 2304 + kp * PKK + c4 * 4) * 4u;
            CPA16(sbase + soH, &g_KTh[gk]);
            CPA16(sbase + soL, &g_KTl[gk]);
        }
        asm volatile("cp.async.commit_group;");
    };

    issueK(0);

    for (int kc = 0; kc < nch; kc++) {
        const int s0 = kc * 64;
        if (kc + 1 < nch) {
            issueK(kc + 1);
            asm volatile("cp.async.wait_group 1;");
        } else {
            asm volatile("cp.async.wait_group 0;");
        }
        __syncthreads();   // K[cur] ready; previous Estage copy-out complete

        const uint32_t* KH = smu + O_KD + (kc & 1) * 4608;
        const uint32_t* KL = KH + 2304;

        float sc[8][4];
#pragma unroll
        for (int nf = 0; nf < 8; nf++)
#pragma unroll
            for (int j = 0; j < 4; j++) sc[nf][j] = 0.f;

#pragma unroll
        for (int ks = 0; ks < 4; ks++) {
            const int kp0 = ks * 8 + tig, kp1 = kp0 + 4;
            const uint32_t qh0 = smu[O_QH + (band + g) * PQH + kp0];
            const uint32_t qh1 = smu[O_QH + (band + g + 8) * PQH + kp0];
            const uint32_t qh2 = smu[O_QH + (band + g) * PQH + kp1];
            const uint32_t qh3 = smu[O_QH + (band + g + 8) * PQH + kp1];
            const uint32_t ql0 = smu[O_QL + (band + g) * PQH + kp0];
            const uint32_t ql1 = smu[O_QL + (band + g + 8) * PQH + kp0];
            const uint32_t ql2 = smu[O_QL + (band + g) * PQH + kp1];
            const uint32_t ql3 = smu[O_QL + (band + g + 8) * PQH + kp1];
#pragma unroll
            for (int nf = 0; nf < 8; nf++) {
                const uint32_t kh0 = KH[kp0 * PKK + nf * 8 + g];
                const uint32_t kh1 = KH[kp1 * PKK + nf * 8 + g];
                const uint32_t kl0 = KL[kp0 * PKK + nf * 8 + g];
                const uint32_t kl1 = KL[kp1 * PKK + nf * 8 + g];
                MMA16(sc[nf], qh0, qh1, qh2, qh3, kh0, kh1);
                MMA16(sc[nf], qh0, qh1, qh2, qh3, kl0, kl1);
                MMA16(sc[nf], ql0, ql1, ql2, ql3, kh0, kh1);
            }
        }

        // causal mask + chunk max
        float cm0 = -1e30f, cm1 = -1e30f;
#pragma unroll
        for (int nf = 0; nf < 8; nf++) {
            const int c01 = s0 + nf * 8 + 2 * tig;
            if (c01     > row0) sc[nf][0] = -1e30f;
            if (c01 + 1 > row0) sc[nf][1] = -1e30f;
            if (c01     > row1) sc[nf][2] = -1e30f;
            if (c01 + 1 > row1) sc[nf][3] = -1e30f;
            cm0 = fmaxf(cm0, fmaxf(sc[nf][0], sc[nf][1]));
            cm1 = fmaxf(cm1, fmaxf(sc[nf][2], sc[nf][3]));
        }
        cm0 = fmaxf(cm0, __shfl_xor_sync(0xffffffffu, cm0, 1));
        cm0 = fmaxf(cm0, __shfl_xor_sync(0xffffffffu, cm0, 2));
        cm1 = fmaxf(cm1, __shfl_xor_sync(0xffffffffu, cm1, 1));
        cm1 = fmaxf(cm1, __shfl_xor_sync(0xffffffffu, cm1, 2));
        const float cmc0 = fmaxf(cm0, -1e20f);
        const float cmc1 = fmaxf(cm1, -1e20f);

        // E = exp(s - cmc) -> smem staging; accumulate chunk sums
        float se0 = 0.f, se1 = 0.f;
#pragma unroll
        for (int nf = 0; nf < 8; nf++) {
            const float e0 = __expf(sc[nf][0] - cmc0);
            const float e1 = __expf(sc[nf][1] - cmc0);
            const float e2 = __expf(sc[nf][2] - cmc1);
            const float e3 = __expf(sc[nf][3] - cmc1);
            *(float2*)&smf[O_ES + (band + g) * PE + nf * 8 + 2 * tig]     = make_float2(e0, e1);
            *(float2*)&smf[O_ES + (band + g + 8) * PE + nf * 8 + 2 * tig] = make_float2(e2, e3);
            se0 += e0 + e1;
            se1 += e2 + e3;
        }
        se0 += __shfl_xor_sync(0xffffffffu, se0, 1);
        se0 += __shfl_xor_sync(0xffffffffu, se0, 2);
        se1 += __shfl_xor_sync(0xffffffffu, se1, 1);
        se1 += __shfl_xor_sync(0xffffffffu, se1, 2);

        const float mn0 = fmaxf(m0, cm0), mn1 = fmaxf(m1, cm1);
        l0 = l0 * __expf(m0 - mn0) + se0 * __expf(cmc0 - mn0);
        l1 = l1 * __expf(m1 - mn1) + se1 * __expf(cmc1 - mn1);
        m0 = mn0; m1 = mn1;

        if (tig == 0) {
            g_cm[cb + (size_t)kc * 128 + band + g]     = cmc0;
            g_cm[cb + (size_t)kc * 128 + band + g + 8] = cmc1;
        }
        __syncthreads();   // Estage complete

        // coalesced copy-out: 128 rows x 64 floats
#pragma unroll
        for (int i = 0; i < 8; i++) {
            const int idx = tid + i * 256;
            const int r = idx >> 4, c4 = idx & 15;
            *(float4*)&Prow[(size_t)r * SEQ + s0 + c4 * 4] =
                *(const float4*)&smf[O_ES + r * PE + c4 * 4];
        }
    }

    // all warps must finish the final Estage copy-out before MR/LI
    // (O_MR/O_LI alias Estage rows 122-127).
    __syncthreads();

    // per-row stats to smem
    if (tig == 0) {
        smf[O_MR + band + g]     = m0;
        smf[O_MR + band + g + 8] = m1;
        smf[O_LI + band + g]     = 1.f / l0;
        smf[O_LI + band + g + 8] = 1.f / l1;
    }
    __syncthreads();   // all warps done with pass-1 regions before overlay reuse

    // =============================== PASS 2 ===============================
    auto issue2 = [&](int kc) {
        const int buf = kc & 1;
        const int s0 = kc * 64;
        // E chunk: 128 rows x 64 floats
#pragma unroll
        for (int i = 0; i < 8; i++) {
            const int idx = tid + i * 256;
            const int r = idx >> 4, c4 = idx & 15;
            const uint32_t so = (uint32_t)(O_E + buf * 8704 + r * PE + c4 * 4) * 4u;
            CPA16(sbase + so, &Prow[(size_t)r * SEQ + s0 + c4 * 4]);
        }
        // V chunk: 64 rows x 64 words (tf32)
#pragma unroll
        for (int i = 0; i < 4; i++) {
            const int idx = tid + i * 256;
            const int key = idx >> 4, c4 = idx & 15;
            const uint32_t so = (uint32_t)(O_V2 + buf * 4608 + key * PVV + c4 * 4) * 4u;
            CPA16(sbase + so, &g_Vt[((size_t)bh * SEQ + s0 + key) * HD + c4 * 4]);
        }
        asm volatile("cp.async.commit_group;");
    };

    float co[8][4];
#pragma unroll
    for (int df = 0; df < 8; df++)
#pragma unroll
        for (int j = 0; j < 4; j++) co[df][j] = 0.f;

    issue2(0);

    for (int kc = 0; kc < nch; kc++) {
        const int s0 = kc * 64;
        if (kc + 1 < nch) {
            issue2(kc + 1);
            asm volatile("cp.async.wait_group 1;");
        } else {
            asm volatile("cp.async.wait_group 0;");
        }
        __syncthreads();

        // per-row rescale factor for this chunk
        if (tid < 128)
            smf[O_MF + tid] = __expf(g_cm[cb + (size_t)kc * 128 + tid] - smf[O_MR + tid]) * smf[O_LI + tid];
        __syncthreads();

        const float* Eb = smf + O_E + (kc & 1) * 8704;
        const uint32_t* Vb = smu + O_V2 + (kc & 1) * 4608;

        // write P = f * E back to attw
#pragma unroll
        for (int i = 0; i < 8; i++) {
            const int idx = tid + i * 256;
            const int r = idx >> 4, c4 = idx & 15;
            float4 e4 = *(const float4*)&Eb[r * PE + c4 * 4];
            const float f = smf[O_MF + r];
            e4.x *= f; e4.y *= f; e4.z *= f; e4.w *= f;
            *(float4*)&Prow[(size_t)r * SEQ + s0 + c4 * 4] = e4;
        }

        // X = E @ V (1x tf32), then co += f * X
        float X[8][4];
#pragma unroll
        for (int df = 0; df < 8; df++)
#pragma unroll
            for (int j = 0; j < 4; j++) X[df][j] = 0.f;

#pragma unroll
        for (int k8 = 0; k8 < 8; k8++) {
            const int ka = k8 * 8 + tig;
            const uint32_t a0 = f2tf32(Eb[(band + g) * PE + ka]);
            const uint32_t a1 = f2tf32(Eb[(band + g + 8) * PE + ka]);
            const uint32_t a2 = f2tf32(Eb[(band + g) * PE + ka + 4]);
            const uint32_t a3 = f2tf32(Eb[(band + g + 8) * PE + ka + 4]);
#pragma unroll
            for (int df = 0; df < 8; df++) {
                const uint32_t b0 = Vb[ka * PVV + df * 8 + g];
                const uint32_t b1 = Vb[(ka + 4) * PVV + df * 8 + g];
                MMA8(X[df], a0, a1, a2, a3, b0, b1);
            }
        }
        const float f0 = smf[O_MF + band + g];
        const float f1 = smf[O_MF + band + g + 8];
#pragma unroll
        for (int df = 0; df < 8; df++) {
            co[df][0] += f0 * X[df][0];
            co[df][1] += f0 * X[df][1];
            co[df][2] += f1 * X[df][2];
            co[df][3] += f1 * X[df][3];
        }
        __syncthreads();   // protect buffers before next issue
    }

    // ---- zero tail of attention_weights ----
    {
        const int ztail = nch * 64;                // == q0 + 128
        const int ncol4 = (SEQ - ztail) >> 2;
        const float4 z = make_float4(0.f, 0.f, 0.f, 0.f);
        for (int idx = tid; idx < 128 * ncol4; idx += 256) {
            const int r = idx / ncol4, c = idx - r * ncol4;
            *(float4*)&Prow[(size_t)r * SEQ + ztail + c * 4] = z;
        }
    }

    // ---- write O packed+transposed for gemm1: [k/2][m] hi/lo ----
    {
        const int b = bh >> 4, h = bh & 15;
        const int mm0 = b * SEQ + row0;
        const int mm1 = mm0 + 8;
#pragma unroll
        for (int df = 0; df < 8; df++) {
            const size_t kp = (size_t)(h * 32 + df * 4 + tig);
            uint32_t hi, lo;
            split_pack(co[df][0], co[df][1], hi, lo);
            g_aoth[kp * M1 + mm0] = hi;
            g_aotl[kp * M1 + mm0] = lo;
            split_pack(co[df][2], co[df][3], hi, lo);
            g_aoth[kp * M1 + mm1] = hi;
            g_aotl[kp * M1 + mm1] = lo;
        }
    }
}

// ---------------------------------------------------------------------------
extern "C" void kernel_launch(void* const* d_in, const int* in_sizes, int n_in,
                              void* d_out, int out_size)
{
    const float* x    = (const float*)d_in[0];
    const float* Wqkv = (const float*)d_in[1];
    const float* bqkv = (const float*)d_in[2];
    const float* Wout = (const float*)d_in[3];
    const float* bout = (const float*)d_in[4];

    float* out  = (float*)d_out;
    float* attw = out + (size_t)BATCH * SEQ * EMB;

    uint32_t *p_xth, *p_xtl, *p_aoth, *p_aotl, *p_wqh, *p_wql, *p_woh, *p_wol;
    cudaGetSymbolAddress((void**)&p_xth,  g_xth);
    cudaGetSymbolAddress((void**)&p_xtl,  g_xtl);
    cudaGetSymbolAddress((void**)&p_aoth, g_aoth);
    cudaGetSymbolAddress((void**)&p_aotl, g_aotl);
    cudaGetSymbolAddress((void**)&p_wqh,  g_wqh);
    cudaGetSymbolAddress((void**)&p_wql,  g_wql);
    cudaGetSymbolAddress((void**)&p_woh,  g_woh);
    cudaGetSymbolAddress((void**)&p_wol,  g_wol);

    const int gsmem = 8 * 16 * PA * (int)sizeof(uint32_t);   // 69632
    cudaFuncSetAttribute(gemm_bf<0>, cudaFuncAttributeMaxDynamicSharedMemorySize, gsmem);
    cudaFuncSetAttribute(gemm_bf<1>, cudaFuncAttributeMaxDynamicSharedMemorySize, gsmem);
    const int asmem = ATTN_SMEM_F * (int)sizeof(float);      // 108544
    cudaFuncSetAttribute(attn7, cudaFuncAttributeMaxDynamicSharedMemorySize, asmem);

    // prep: pack weights + pack-transpose x
    split_w<<<((KDIM / 2) * (N1 / 4) + 255) / 256, 256>>>(Wqkv, p_wqh, p_wql, N1, (KDIM / 2) * (N1 / 4));
    split_w<<<((KDIM / 2) * (EMB / 4) + 255) / 256, 256>>>(Wout, p_woh, p_wol, EMB, (KDIM / 2) * (EMB / 4));
    split_t<<<dim3(KDIM / 32, M1 / 32), 256>>>(x, p_xth, p_xtl, M1, KDIM);

    // 1) QKV projection -> packed Q / packed K^T / tf32 V
    gemm_bf<0><<<dim3(N1 / 128, M1 / 128), 256, gsmem>>>(p_xth, p_xtl, p_wqh, p_wql, bqkv, nullptr, M1, N1, KDIM);

    // 2) fused causal attention (writes attention_weights + packed AO^T)
    attn7<<<dim3(SEQ / 128, BATCH * NH), 256, asmem>>>(attw);

    // 3) output projection
    gemm_bf<1><<<dim3(EMB / 128, M1 / 128), 256, gsmem>>>(p_aoth, p_aotl, p_woh, p_wol, bout, out, M1, EMB, KDIM);
}